// round 14
// baseline (speedup 1.0000x reference)
#include <cuda_runtime.h>
#include <cuda_fp16.h>
#include <cstdint>

#define BATCH 32
#define SEQ   2048
#define DIM   128
#define BR    64
#define BC    64
#define NKV   (SEQ/BC)     // 32
#define THREADS 256

// ---------------- f16 scratch (pre-converted, both row-major) ----------------
__device__ __half g_k16[(size_t)BATCH*SEQ*DIM];   // [b][s][d]
__device__ __half g_v16[(size_t)BATCH*SEQ*DIM];   // [b][s][d]

// ---------------- smem layout ----------------
// strides in halves; 136*2=272B, 72*2=144B (odd 16B multiples) -> conflict-free ldmatrix
#define QSTR 136
#define KSTR 136
#define PSTR 72

#define KBUF 17408                        // 64*136*2
#define PBUF 9216                         // 64*72*2
#define SM_Q   0
#define SM_K   17408                      // 2 x KBUF
#define SM_V   (SM_K + 2*KBUF)            // 2 x KBUF (V data cols 0..127; col 128 = ones)
#define SM_P   (SM_V + 2*KBUF)            // 2 x PBUF
#define SM_L   (SM_P + 2*PBUF)
#define SMEM_BYTES (SM_L + 512)           // ~106 KB -> 2 CTAs/SM

// named barriers: 1,2 = P-full (buf0/1); 3,4 = P-free; 5 = A-internal; 6 = B-internal
#define BAR_SYNC(id,cnt)   asm volatile("bar.sync %0, %1;"   :: "r"(id), "r"(cnt) : "memory")
#define BAR_ARRIVE(id,cnt) asm volatile("bar.arrive %0, %1;" :: "r"(id), "r"(cnt) : "memory")

static __device__ __forceinline__ uint32_t h2u(__half2 h) { return *reinterpret_cast<uint32_t*>(&h); }

// pack two f32 into f16x2: lo=a, hi=b
static __device__ __forceinline__ uint32_t cvt_f16x2(float hi, float lo) {
    uint32_t r;
    asm volatile("cvt.rn.f16x2.f32 %0, %1, %2;" : "=r"(r) : "f"(hi), "f"(lo));
    return r;
}
static __device__ __forceinline__ uint32_t ex2_f16x2(uint32_t x) {
    uint32_t r;
    asm volatile("ex2.approx.f16x2 %0, %1;" : "=r"(r) : "r"(x));
    return r;
}

static __device__ __forceinline__ void mma16816(
    float& c0, float& c1, float& c2, float& c3,
    uint32_t a0, uint32_t a1, uint32_t a2, uint32_t a3,
    uint32_t b0, uint32_t b1)
{
    asm volatile(
        "mma.sync.aligned.m16n8k16.row.col.f32.f16.f16.f32 "
        "{%0,%1,%2,%3}, {%4,%5,%6,%7}, {%8,%9}, {%0,%1,%2,%3};"
        : "+f"(c0), "+f"(c1), "+f"(c2), "+f"(c3)
        : "r"(a0), "r"(a1), "r"(a2), "r"(a3), "r"(b0), "r"(b1));
}
static __device__ __forceinline__ void ldsm_x4(uint32_t& r0, uint32_t& r1,
                                               uint32_t& r2, uint32_t& r3, uint32_t addr)
{
    asm volatile("ldmatrix.sync.aligned.m8n8.x4.shared.b16 {%0,%1,%2,%3}, [%4];"
        : "=r"(r0), "=r"(r1), "=r"(r2), "=r"(r3) : "r"(addr));
}
static __device__ __forceinline__ void ldsm_x4_t(uint32_t& r0, uint32_t& r1,
                                                 uint32_t& r2, uint32_t& r3, uint32_t addr)
{
    asm volatile("ldmatrix.sync.aligned.m8n8.x4.trans.shared.b16 {%0,%1,%2,%3}, [%4];"
        : "=r"(r0), "=r"(r1), "=r"(r2), "=r"(r3) : "r"(addr));
}
static __device__ __forceinline__ void ldsm_x2_t(uint32_t& r0, uint32_t& r1, uint32_t addr)
{
    asm volatile("ldmatrix.sync.aligned.m8n8.x2.trans.shared.b16 {%0,%1}, [%2];"
        : "=r"(r0), "=r"(r1) : "r"(addr));
}
static __device__ __forceinline__ void cpa16(uint32_t dst, const void* src) {
    asm volatile("cp.async.cg.shared.global [%0], [%1], 16;" :: "r"(dst), "l"(src));
}
#define CPASYNC_COMMIT()   asm volatile("cp.async.commit_group;" ::: "memory")
#define CPASYNC_WAIT_ALL() asm volatile("cp.async.wait_group 0;" ::: "memory")

// ---------------- pre-convert kernel ----------------
__global__ void cvt_kv_kernel(const float* __restrict__ K, const float* __restrict__ V) {
    size_t i = (size_t)blockIdx.x * 256 + threadIdx.x;   // float4 units
    float4 fk = ((const float4*)K)[i];
    float4 fv = ((const float4*)V)[i];
    ((__half2*)g_k16)[2*i]   = __floats2half2_rn(fk.x, fk.y);
    ((__half2*)g_k16)[2*i+1] = __floats2half2_rn(fk.z, fk.w);
    ((__half2*)g_v16)[2*i]   = __floats2half2_rn(fv.x, fv.y);
    ((__half2*)g_v16)[2*i+1] = __floats2half2_rn(fv.z, fv.w);
}

// ---------------- half-group tile loads (128 threads each) ----------------
static __device__ __forceinline__ void load_k(int b, int tile, uint32_t smb, int t128) {
    const __half* gk = g_k16 + (size_t)b*SEQ*DIM + (size_t)tile*BC*DIM;
    uint32_t kb = smb + SM_K + (tile & 1) * KBUF;
    #pragma unroll
    for (int i = 0; i < 8; i++) {           // 64 rows x 16 chunks of 16B
        int c = t128 + i * 128;
        int row = c >> 4, ch = c & 15;
        cpa16(kb + row*(KSTR*2) + ch*16, gk + row*DIM + ch*8);
    }
}
static __device__ __forceinline__ void load_v(int b, int tile, uint32_t smb, int t128) {
    const __half* gv = g_v16 + (size_t)b*SEQ*DIM + (size_t)tile*BC*DIM;
    uint32_t vb = smb + SM_V + (tile & 1) * KBUF;
    #pragma unroll
    for (int i = 0; i < 8; i++) {
        int c = t128 + i * 128;
        int row = c >> 4, ch = c & 15;
        cpa16(vb + row*(KSTR*2) + ch*16, gv + row*DIM + ch*8);
    }
}

// ---------------- main kernel (warp-specialized, l via ones-column MMA) ----------------
__global__ void __launch_bounds__(THREADS, 2)
fa_ws_kernel(const float* __restrict__ Q, float* __restrict__ Out)
{
    extern __shared__ __align__(16) char smem[];
    const uint32_t smb = (uint32_t)__cvta_generic_to_shared(smem);

    const int tid  = threadIdx.x;
    const int warp = tid >> 5;
    const int lane = tid & 31;
    const int g    = lane >> 2;
    const int q4   = lane & 3;
    const bool isA = warp < 4;
    const int w4   = warp & 3;
    const int mq   = w4 >> 1;           // 32-row strip (0/1)
    const int nq   = w4 & 1;            // A: key half / B: d half

    const int qt = blockIdx.x;
    const int b  = blockIdx.y;

    // 1/sqrt(128) * log2(e)
    const float QK_SCALE = 0.08838834764831845f * 1.4426950408889634f;

    // ---- prologue: Q (all), ones-pad for V (col 128 = 1.0, both buffers) ----
    {
        const float* qg = Q + ((size_t)b*SEQ + (size_t)qt*BR) * DIM;
        #pragma unroll
        for (int i = 0; i < 8; i++) {
            int u = tid + i*THREADS;          // 2048 float4 units
            int row = u >> 5, c4 = u & 31;
            float4 f = __ldg((const float4*)(qg + row*DIM + c4*4));
            uint32_t w0 = h2u(__floats2half2_rn(f.x*QK_SCALE, f.y*QK_SCALE));
            uint32_t w1 = h2u(__floats2half2_rn(f.z*QK_SCALE, f.w*QK_SCALE));
            uint32_t dst = smb + SM_Q + row*(QSTR*2) + c4*8;
            asm volatile("st.shared.v2.b32 [%0], {%1,%2};" :: "r"(dst), "r"(w0), "r"(w1));
        }
        if (tid < 128) {                     // 2 buffers x 64 rows: cols 128..135
            int row = tid & 63, vbuf = tid >> 6;
            uint32_t dst = smb + SM_V + vbuf*KBUF + row*(KSTR*2) + 128*2;
            asm volatile("st.shared.v4.b32 [%0], {%1,%2,%3,%4};"
                :: "r"(dst), "r"(0x00003C00u), "r"(0u), "r"(0u), "r"(0u));
        }
    }
    if (isA) load_k(b, 0, smb, tid);
    else     load_v(b, 0, smb, tid - 128);
    CPASYNC_COMMIT();
    CPASYNC_WAIT_ALL();
    __syncthreads();

    // fragment lane patterns
    const int brow  = ((lane >> 4) << 3) + (lane & 7);
    const int bcolh = 8 * ((lane >> 3) & 1);
    const int arow  = 8 * ((lane >> 3) & 1) + (lane & 7);
    const int acolh = 8 * (lane >> 4);

    if (isA) {
        // ========= GROUP A: QK (32 rows x 32 keys per warp) + softmax -> P =========
        const uint32_t kfrag = (uint32_t)((nq*32 + brow) * (KSTR*2) + bcolh*2);

        uint32_t qf[2][8][4];
        #pragma unroll
        for (int mt = 0; mt < 2; mt++) {
            uint32_t qb = smb + SM_Q + (uint32_t)((mq*32 + mt*16 + arow)*(QSTR*2) + acolh*2);
            #pragma unroll
            for (int kt = 0; kt < 8; kt++)
                ldsm_x4(qf[mt][kt][0], qf[mt][kt][1], qf[mt][kt][2], qf[mt][kt][3],
                        qb + kt*32);
        }

        #pragma unroll 1
        for (int it = 0; it < NKV; it++) {
            const int buf = it & 1;
            if (it + 1 < NKV) load_k(b, it + 1, smb, tid);
            CPASYNC_COMMIT();

            // QK: S[32 rows x 32 keys]
            float c[2][4][4];
            #pragma unroll
            for (int mt = 0; mt < 2; mt++)
                #pragma unroll
                for (int nt = 0; nt < 4; nt++)
                    { c[mt][nt][0]=0.f; c[mt][nt][1]=0.f; c[mt][nt][2]=0.f; c[mt][nt][3]=0.f; }

            const uint32_t kb = smb + SM_K + buf*KBUF + kfrag;
            #pragma unroll
            for (int kt = 0; kt < 8; kt++) {
                #pragma unroll
                for (int nt2 = 0; nt2 < 2; nt2++) {
                    uint32_t b00, b01, b10, b11;
                    ldsm_x4(b00, b01, b10, b11, kb + nt2*(16*KSTR*2) + kt*32);
                    #pragma unroll
                    for (int mt = 0; mt < 2; mt++) {
                        mma16816(c[mt][2*nt2][0], c[mt][2*nt2][1], c[mt][2*nt2][2], c[mt][2*nt2][3],
                                 qf[mt][kt][0], qf[mt][kt][1], qf[mt][kt][2], qf[mt][kt][3], b00, b01);
                        mma16816(c[mt][2*nt2+1][0], c[mt][2*nt2+1][1], c[mt][2*nt2+1][2], c[mt][2*nt2+1][3],
                                 qf[mt][kt][0], qf[mt][kt][1], qf[mt][kt][2], qf[mt][kt][3], b10, b11);
                    }
                }
            }

            // wait until B freed this P buffer (consumed it-2)
            if (it >= 2) BAR_SYNC(3 + buf, 256);

            // softmax numerator -> P: f32 pair -> f16x2 -> ex2.f16x2 -> STS
            #pragma unroll
            for (int mt = 0; mt < 2; mt++) {
                uint32_t pr0 = smb + SM_P + buf*PBUF
                             + (uint32_t)((mq*32 + mt*16 + g)*(PSTR*2) + (nq*32 + 2*q4)*2);
                #pragma unroll
                for (int nt = 0; nt < 4; nt++) {
                    uint32_t s0 = cvt_f16x2(c[mt][nt][1], c[mt][nt][0]);  // row g
                    uint32_t s1 = cvt_f16x2(c[mt][nt][3], c[mt][nt][2]);  // row g+8
                    uint32_t p0 = ex2_f16x2(s0);
                    uint32_t p1 = ex2_f16x2(s1);
                    asm volatile("st.shared.b32 [%0], %1;" :: "r"(pr0 + nt*16), "r"(p0));
                    asm volatile("st.shared.b32 [%0], %1;" :: "r"(pr0 + 8*(PSTR*2) + nt*16), "r"(p1));
                }
            }

            CPASYNC_WAIT_ALL();       // K(it+1) landed
            BAR_SYNC(5, 128);         // A-internal: K visibility + P stores done
            BAR_ARRIVE(1 + buf, 256); // signal P(buf) full
        }
        __syncthreads();
    } else {
        // ========= GROUP B: PV (32 rows x 64 d per warp) + l via ones column =========
        const uint32_t vfrag = (uint32_t)(arow * (KSTR*2) + (nq*64 + acolh)*2);
        const int vl = lane & 15;       // row index for x2 trans ldmatrix

        float o[2][8][4];
        #pragma unroll
        for (int mt = 0; mt < 2; mt++)
            #pragma unroll
            for (int nt = 0; nt < 8; nt++)
                { o[mt][nt][0]=0.f; o[mt][nt][1]=0.f; o[mt][nt][2]=0.f; o[mt][nt][3]=0.f; }
        float lf[2][4];
        #pragma unroll
        for (int mt = 0; mt < 2; mt++)
            { lf[mt][0]=0.f; lf[mt][1]=0.f; lf[mt][2]=0.f; lf[mt][3]=0.f; }

        #pragma unroll 1
        for (int it = 0; it < NKV; it++) {
            const int buf = it & 1;
            if (it + 1 < NKV) load_v(b, it + 1, smb, tid - 128);
            CPASYNC_COMMIT();

            BAR_SYNC(1 + buf, 256);   // wait P(buf) full

            const uint32_t vb  = smb + SM_V + buf*KBUF + vfrag;
            const uint32_t vb1 = smb + SM_V + buf*KBUF + 128*2;   // ones column base
            const uint32_t pb0 = smb + SM_P + buf*PBUF
                               + (uint32_t)((mq*32 + arow)*(PSTR*2) + acolh*2);
            #pragma unroll
            for (int kt = 0; kt < 4; kt++) {
                uint32_t pa[2][4];
                #pragma unroll
                for (int mt = 0; mt < 2; mt++)
                    ldsm_x4(pa[mt][0], pa[mt][1], pa[mt][2], pa[mt][3],
                            pb0 + mt*(16*PSTR*2) + kt*32);
                #pragma unroll
                for (int nt2 = 0; nt2 < 4; nt2++) {
                    uint32_t b0a, b1a, b0b, b1b;
                    ldsm_x4_t(b0a, b1a, b0b, b1b, vb + kt*(16*KSTR*2) + nt2*32);
                    #pragma unroll
                    for (int mt = 0; mt < 2; mt++) {
                        mma16816(o[mt][2*nt2][0], o[mt][2*nt2][1], o[mt][2*nt2][2], o[mt][2*nt2][3],
                                 pa[mt][0], pa[mt][1], pa[mt][2], pa[mt][3], b0a, b1a);
                        mma16816(o[mt][2*nt2+1][0], o[mt][2*nt2+1][1], o[mt][2*nt2+1][2], o[mt][2*nt2+1][3],
                                 pa[mt][0], pa[mt][1], pa[mt][2], pa[mt][3], b0b, b1b);
                    }
                }
                if (nq == 0) {  // row sums: P @ ones-column (accumulates across all tiles)
                    uint32_t l0, l1;
                    ldsm_x2_t(l0, l1, vb1 + (kt*16 + vl)*(KSTR*2));
                    #pragma unroll
                    for (int mt = 0; mt < 2; mt++)
                        mma16816(lf[mt][0], lf[mt][1], lf[mt][2], lf[mt][3],
                                 pa[mt][0], pa[mt][1], pa[mt][2], pa[mt][3], l0, l1);
                }
            }

            BAR_ARRIVE(3 + buf, 256); // P(buf) free
            CPASYNC_WAIT_ALL();       // V(it+1) landed
            BAR_SYNC(6, 128);         // B-internal: V visibility
        }

        // publish row sums (col 128 lives in q4==0 lanes: c0=row g, c2=row g+8)
        float* lsh = (float*)(smem + SM_L);
        if (nq == 0 && q4 == 0) {
            #pragma unroll
            for (int mt = 0; mt < 2; mt++) {
                lsh[mq*32 + mt*16 + g]     = lf[mt][0];
                lsh[mq*32 + mt*16 + g + 8] = lf[mt][2];
            }
        }
        __syncthreads();

        #pragma unroll
        for (int mt = 0; mt < 2; mt++) {
            int r0 = mq*32 + mt*16 + g;
            float inv0 = 1.0f / lsh[r0];
            float inv1 = 1.0f / lsh[r0 + 8];
            float* op0 = Out + ((size_t)b*SEQ + (size_t)qt*BR + r0) * DIM + nq*64 + 2*q4;
            float* op1 = op0 + 8*DIM;
            #pragma unroll
            for (int nt = 0; nt < 8; nt++) {
                *(float2*)(op0 + nt*8) = make_float2(o[mt][nt][0]*inv0, o[mt][nt][1]*inv0);
                *(float2*)(op1 + nt*8) = make_float2(o[mt][nt][2]*inv1, o[mt][nt][3]*inv1);
            }
        }
    }
}

extern "C" void kernel_launch(void* const* d_in, const int* in_sizes, int n_in,
                              void* d_out, int out_size) {
    const float* q = (const float*)d_in[0];
    const float* k = (const float*)d_in[1];
    const float* v = (const float*)d_in[2];
    float* o = (float*)d_out;

    cvt_kv_kernel<<<(int)(((size_t)BATCH*SEQ*DIM/4)/256), 256>>>(k, v);

    cudaFuncSetAttribute(fa_ws_kernel,
                         cudaFuncAttributeMaxDynamicSharedMemorySize, SMEM_BYTES);
    dim3 grid(SEQ/BR, BATCH);
    fa_ws_kernel<<<grid, THREADS, SMEM_BYTES>>>(q, o);
}

// round 15
// speedup vs baseline: 1.0507x; 1.0507x over previous
#include <cuda_runtime.h>
#include <cuda_fp16.h>
#include <cstdint>

#define BATCH 32
#define SEQ   2048
#define DIM   128
#define BR    64
#define BC    64
#define NKV   (SEQ/BC)     // 32
#define THREADS 256

// ---------------- f16 scratch (pre-converted, both row-major) ----------------
__device__ __half g_k16[(size_t)BATCH*SEQ*DIM];   // [b][s][d]
__device__ __half g_v16[(size_t)BATCH*SEQ*DIM];   // [b][s][d]

// ---------------- smem layout ----------------
// strides in halves; 136*2=272B, 72*2=144B (odd 16B multiples) -> conflict-free ldmatrix
#define QSTR 136
#define KSTR 136
#define PSTR 72
#define OSTR 132                          // f32 epilogue exchange stride

#define KBUF 17408                        // 64*136*2
#define PBUF 9216                         // 64*72*2
#define SM_Q   0                          // 34816
#define SM_K   34816                      // 4 x KBUF (tile&3)
#define SM_V   (SM_K + 4*KBUF)            // 4 x KBUF
#define SM_P   (SM_V + 4*KBUF)            // 2 x PBUF (per group)
#define SM_L   (SM_P + 2*PBUF)            // 256 floats
#define SM_OB  SM_K                       // epilogue O exchange (64*132*4 = 33792)
#define SMEM_BYTES (SM_L + 1024)          // 193536 -> 1 CTA/SM

// named barriers: 1 = group A internal; 2 = group B internal; 3 = stagger
#define BAR_SYNC(id,cnt)   asm volatile("bar.sync %0, %1;"   :: "r"(id), "r"(cnt) : "memory")
#define BAR_ARRIVE(id,cnt) asm volatile("bar.arrive %0, %1;" :: "r"(id), "r"(cnt) : "memory")

static __device__ __forceinline__ float ex2(float x) {
    float y; asm volatile("ex2.approx.ftz.f32 %0, %1;" : "=f"(y) : "f"(x)); return y;
}
static __device__ __forceinline__ uint32_t h2u(__half2 h) { return *reinterpret_cast<uint32_t*>(&h); }

static __device__ __forceinline__ void mma16816(
    float& c0, float& c1, float& c2, float& c3,
    uint32_t a0, uint32_t a1, uint32_t a2, uint32_t a3,
    uint32_t b0, uint32_t b1)
{
    asm volatile(
        "mma.sync.aligned.m16n8k16.row.col.f32.f16.f16.f32 "
        "{%0,%1,%2,%3}, {%4,%5,%6,%7}, {%8,%9}, {%0,%1,%2,%3};"
        : "+f"(c0), "+f"(c1), "+f"(c2), "+f"(c3)
        : "r"(a0), "r"(a1), "r"(a2), "r"(a3), "r"(b0), "r"(b1));
}
static __device__ __forceinline__ void ldsm_x4(uint32_t& r0, uint32_t& r1,
                                               uint32_t& r2, uint32_t& r3, uint32_t addr)
{
    asm volatile("ldmatrix.sync.aligned.m8n8.x4.shared.b16 {%0,%1,%2,%3}, [%4];"
        : "=r"(r0), "=r"(r1), "=r"(r2), "=r"(r3) : "r"(addr));
}
static __device__ __forceinline__ void ldsm_x4_t(uint32_t& r0, uint32_t& r1,
                                                 uint32_t& r2, uint32_t& r3, uint32_t addr)
{
    asm volatile("ldmatrix.sync.aligned.m8n8.x4.trans.shared.b16 {%0,%1,%2,%3}, [%4];"
        : "=r"(r0), "=r"(r1), "=r"(r2), "=r"(r3) : "r"(addr));
}
static __device__ __forceinline__ void cpa16(uint32_t dst, const void* src) {
    asm volatile("cp.async.cg.shared.global [%0], [%1], 16;" :: "r"(dst), "l"(src));
}
#define CPASYNC_COMMIT()   asm volatile("cp.async.commit_group;" ::: "memory")
#define CPASYNC_WAIT0()    asm volatile("cp.async.wait_group 0;" ::: "memory")

// ---------------- pre-convert kernel ----------------
__global__ void cvt_kv_kernel(const float* __restrict__ K, const float* __restrict__ V) {
    size_t i = (size_t)blockIdx.x * 256 + threadIdx.x;   // float4 units
    float4 fk = ((const float4*)K)[i];
    float4 fv = ((const float4*)V)[i];
    ((__half2*)g_k16)[2*i]   = __floats2half2_rn(fk.x, fk.y);
    ((__half2*)g_k16)[2*i+1] = __floats2half2_rn(fk.z, fk.w);
    ((__half2*)g_v16)[2*i]   = __floats2half2_rn(fv.x, fv.y);
    ((__half2*)g_v16)[2*i+1] = __floats2half2_rn(fv.z, fv.w);
}

// ---------------- K+V tile load into buf (tile&3), 128 threads ----------------
static __device__ __forceinline__ void load_kv(int b, int tile, uint32_t smb, int t128) {
    const size_t off = (size_t)b*SEQ*DIM + (size_t)tile*BC*DIM;
    const __half* gk = g_k16 + off;
    const __half* gv = g_v16 + off;
    uint32_t kb = smb + SM_K + (tile & 3) * KBUF;
    uint32_t vb = smb + SM_V + (tile & 3) * KBUF;
    #pragma unroll
    for (int i = 0; i < 8; i++) {           // 64 rows x 16 chunks of 16B
        int c = t128 + i * 128;
        int row = c >> 4, ch = c & 15;
        cpa16(kb + row*(KSTR*2) + ch*16, gk + row*DIM + ch*8);
        cpa16(vb + row*(KSTR*2) + ch*16, gv + row*DIM + ch*8);
    }
}

// ---------------- main kernel: role-alternating groups by tile parity ----------------
__global__ void __launch_bounds__(THREADS, 1)
fa_alt_kernel(const float* __restrict__ Q, float* __restrict__ Out)
{
    extern __shared__ __align__(16) char smem[];
    const uint32_t smb = (uint32_t)__cvta_generic_to_shared(smem);

    const int tid  = threadIdx.x;
    const int warp = tid >> 5;
    const int lane = tid & 31;
    const int g    = lane >> 2;
    const int q4   = lane & 3;
    const int gid  = warp >> 2;         // 0: even tiles, 1: odd tiles
    const int w4   = warp & 3;
    const int mq   = w4 >> 1;           // 32-row strip
    const int nq   = w4 & 1;            // key half (QK) / d half (PV)
    const int t128 = tid & 127;

    const int qt = blockIdx.x;
    const int b  = blockIdx.y;

    // 1/sqrt(128) * log2(e)
    const float QK_SCALE = 0.08838834764831845f * 1.4426950408889634f;

    // ---- prologue: Q (all threads, scaled f16), KV(gid) per group ----
    load_kv(b, gid, smb, t128);
    CPASYNC_COMMIT();
    {
        const float* qg = Q + ((size_t)b*SEQ + (size_t)qt*BR) * DIM;
        #pragma unroll
        for (int i = 0; i < 8; i++) {
            int u = tid + i*THREADS;          // 2048 float4 units
            int row = u >> 5, c4 = u & 31;
            float4 f = __ldg((const float4*)(qg + row*DIM + c4*4));
            uint32_t w0 = h2u(__floats2half2_rn(f.x*QK_SCALE, f.y*QK_SCALE));
            uint32_t w1 = h2u(__floats2half2_rn(f.z*QK_SCALE, f.w*QK_SCALE));
            uint32_t dst = smb + SM_Q + row*(QSTR*2) + c4*8;
            asm volatile("st.shared.v2.b32 [%0], {%1,%2};" :: "r"(dst), "r"(w0), "r"(w1));
        }
    }
    __syncthreads();    // Q visible

    // fragment lane patterns
    const int brow  = ((lane >> 4) << 3) + (lane & 7);
    const int bcolh = 8 * ((lane >> 3) & 1);
    const int arow  = 8 * ((lane >> 3) & 1) + (lane & 7);
    const int acolh = 8 * (lane >> 4);

    const uint32_t kfrag = (uint32_t)((nq*32 + brow) * (KSTR*2) + bcolh*2);
    const uint32_t vfrag = (uint32_t)(arow * (KSTR*2) + (nq*64 + acolh)*2);

    // Q A-fragments (32-row strip x 8 k-tiles)
    uint32_t qf[2][8][4];
    #pragma unroll
    for (int mt = 0; mt < 2; mt++) {
        uint32_t qb = smb + SM_Q + (uint32_t)((mq*32 + mt*16 + arow)*(QSTR*2) + acolh*2);
        #pragma unroll
        for (int kt = 0; kt < 8; kt++)
            ldsm_x4(qf[mt][kt][0], qf[mt][kt][1], qf[mt][kt][2], qf[mt][kt][3],
                    qb + kt*32);
    }

    float o[2][8][4];
    #pragma unroll
    for (int mt = 0; mt < 2; mt++)
        #pragma unroll
        for (int nt = 0; nt < 8; nt++)
            { o[mt][nt][0]=0.f; o[mt][nt][1]=0.f; o[mt][nt][2]=0.f; o[mt][nt][3]=0.f; }
    float lr[2][2] = {{0.f,0.f},{0.f,0.f}};

    // stagger: B waits for A to get one QK ahead
    if (gid == 1) BAR_SYNC(3, 256);

    #pragma unroll 1
    for (int i = 0; i < NKV/2; i++) {
        const int t = 2*i + gid;

        CPASYNC_WAIT0();          // own KV(t) loads done (committed 1 period ago)
        BAR_SYNC(1 + gid, 128);   // group: KV(t) visible; PV(t-2)+QK(t-2) complete -> bufs free

        if (t + 2 < NKV) load_kv(b, t + 2, smb, t128);
        CPASYNC_COMMIT();

        // ---- QK: S[32 rows x 32 keys] from kbuf[t&3] ----
        float c[2][4][4];
        #pragma unroll
        for (int mt = 0; mt < 2; mt++)
            #pragma unroll
            for (int nt = 0; nt < 4; nt++)
                { c[mt][nt][0]=0.f; c[mt][nt][1]=0.f; c[mt][nt][2]=0.f; c[mt][nt][3]=0.f; }

        const uint32_t kb = smb + SM_K + (t & 3)*KBUF + kfrag;
        #pragma unroll
        for (int kt = 0; kt < 8; kt++) {
            #pragma unroll
            for (int nt2 = 0; nt2 < 2; nt2++) {
                uint32_t b00, b01, b10, b11;
                ldsm_x4(b00, b01, b10, b11, kb + nt2*(16*KSTR*2) + kt*32);
                #pragma unroll
                for (int mt = 0; mt < 2; mt++) {
                    mma16816(c[mt][2*nt2][0], c[mt][2*nt2][1], c[mt][2*nt2][2], c[mt][2*nt2][3],
                             qf[mt][kt][0], qf[mt][kt][1], qf[mt][kt][2], qf[mt][kt][3], b00, b01);
                    mma16816(c[mt][2*nt2+1][0], c[mt][2*nt2+1][1], c[mt][2*nt2+1][2], c[mt][2*nt2+1][3],
                             qf[mt][kt][0], qf[mt][kt][1], qf[mt][kt][2], qf[mt][kt][3], b10, b11);
                }
            }
        }
        if (gid == 0 && i == 0) BAR_ARRIVE(3, 256);   // release B after first QK

        // ---- softmax numerator -> P(group) ----
        #pragma unroll
        for (int mt = 0; mt < 2; mt++) {
            uint32_t pr0 = smb + SM_P + gid*PBUF
                         + (uint32_t)((mq*32 + mt*16 + g)*(PSTR*2) + (nq*32 + 2*q4)*2);
            #pragma unroll
            for (int nt = 0; nt < 4; nt++) {
                float p0 = ex2(c[mt][nt][0]), p1 = ex2(c[mt][nt][1]);
                float p2 = ex2(c[mt][nt][2]), p3 = ex2(c[mt][nt][3]);
                lr[mt][0] += p0 + p1; lr[mt][1] += p2 + p3;
                uint32_t w0 = h2u(__floats2half2_rn(p0, p1));
                uint32_t w1 = h2u(__floats2half2_rn(p2, p3));
                asm volatile("st.shared.b32 [%0], %1;" :: "r"(pr0 + nt*16), "r"(w0));
                asm volatile("st.shared.b32 [%0], %1;" :: "r"(pr0 + 8*(PSTR*2) + nt*16), "r"(w1));
            }
        }
        BAR_SYNC(1 + gid, 128);   // P written by whole group

        // ---- PV: O[32 rows x 64 d] += P @ V from vbuf[t&3] ----
        const uint32_t vb  = smb + SM_V + (t & 3)*KBUF + vfrag;
        const uint32_t pb0 = smb + SM_P + gid*PBUF
                           + (uint32_t)((mq*32 + arow)*(PSTR*2) + acolh*2);
        #pragma unroll
        for (int kt = 0; kt < 4; kt++) {
            uint32_t pa[2][4];
            #pragma unroll
            for (int mt = 0; mt < 2; mt++)
                ldsm_x4(pa[mt][0], pa[mt][1], pa[mt][2], pa[mt][3],
                        pb0 + mt*(16*PSTR*2) + kt*32);
            #pragma unroll
            for (int nt2 = 0; nt2 < 4; nt2++) {
                uint32_t b0a, b1a, b0b, b1b;
                ldsm_x4_t(b0a, b1a, b0b, b1b, vb + kt*(16*KSTR*2) + nt2*32);
                #pragma unroll
                for (int mt = 0; mt < 2; mt++) {
                    mma16816(o[mt][2*nt2][0], o[mt][2*nt2][1], o[mt][2*nt2][2], o[mt][2*nt2][3],
                             pa[mt][0], pa[mt][1], pa[mt][2], pa[mt][3], b0a, b1a);
                    mma16816(o[mt][2*nt2+1][0], o[mt][2*nt2+1][1], o[mt][2*nt2+1][2], o[mt][2*nt2+1][3],
                             pa[mt][0], pa[mt][1], pa[mt][2], pa[mt][3], b0b, b1b);
                }
            }
        }
    }

    // ---- publish row sums (per group, per key-half) ----
    float* lsh = (float*)(smem + SM_L);
    #pragma unroll
    for (int mt = 0; mt < 2; mt++) {
        float s0 = lr[mt][0], s1 = lr[mt][1];
        s0 += __shfl_xor_sync(0xffffffffu, s0, 1);
        s0 += __shfl_xor_sync(0xffffffffu, s0, 2);
        s1 += __shfl_xor_sync(0xffffffffu, s1, 1);
        s1 += __shfl_xor_sync(0xffffffffu, s1, 2);
        if (q4 == 0) {
            lsh[gid*128 + nq*64 + mq*32 + mt*16 + g]     = s0;
            lsh[gid*128 + nq*64 + mq*32 + mt*16 + g + 8] = s1;
        }
    }
    __syncthreads();

    // ---- epilogue: B -> smem, A combines + normalizes + stores ----
    float* ob = (float*)(smem + SM_OB);
    if (gid == 1) {
        #pragma unroll
        for (int mt = 0; mt < 2; mt++) {
            int r0 = mq*32 + mt*16 + g;
            #pragma unroll
            for (int nt = 0; nt < 8; nt++) {
                int col = nq*64 + nt*8 + 2*q4;
                *(float2*)&ob[r0*OSTR + col]     = make_float2(o[mt][nt][0], o[mt][nt][1]);
                *(float2*)&ob[(r0+8)*OSTR + col] = make_float2(o[mt][nt][2], o[mt][nt][3]);
            }
        }
    }
    __syncthreads();
    if (gid == 0) {
        #pragma unroll
        for (int mt = 0; mt < 2; mt++) {
            int r0 = mq*32 + mt*16 + g;
            float l0 = lsh[r0]   + lsh[64 + r0]   + lsh[128 + r0]   + lsh[192 + r0];
            float l1 = lsh[r0+8] + lsh[64 + r0+8] + lsh[128 + r0+8] + lsh[192 + r0+8];
            float inv0 = 1.0f / l0, inv1 = 1.0f / l1;
            float* op0 = Out + ((size_t)b*SEQ + (size_t)qt*BR + r0) * DIM + nq*64 + 2*q4;
            float* op1 = op0 + 8*DIM;
            #pragma unroll
            for (int nt = 0; nt < 8; nt++) {
                int col = nq*64 + nt*8 + 2*q4;
                float2 e0 = *(float2*)&ob[r0*OSTR + col];
                float2 e1 = *(float2*)&ob[(r0+8)*OSTR + col];
                *(float2*)(op0 + nt*8) = make_float2((o[mt][nt][0]+e0.x)*inv0,
                                                     (o[mt][nt][1]+e0.y)*inv0);
                *(float2*)(op1 + nt*8) = make_float2((o[mt][nt][2]+e1.x)*inv1,
                                                     (o[mt][nt][3]+e1.y)*inv1);
            }
        }
    }
}

extern "C" void kernel_launch(void* const* d_in, const int* in_sizes, int n_in,
                              void* d_out, int out_size) {
    const float* q = (const float*)d_in[0];
    const float* k = (const float*)d_in[1];
    const float* v = (const float*)d_in[2];
    float* o = (float*)d_out;

    cvt_kv_kernel<<<(int)(((size_t)BATCH*SEQ*DIM/4)/256), 256>>>(k, v);

    cudaFuncSetAttribute(fa_alt_kernel,
                         cudaFuncAttributeMaxDynamicSharedMemorySize, SMEM_BYTES);
    dim3 grid(SEQ/BR, BATCH);
    fa_alt_kernel<<<grid, THREADS, SMEM_BYTES>>>(q, o);
}